// round 17
// baseline (speedup 1.0000x reference)
#include <cuda_runtime.h>
#include <cuda_bf16.h>

// ---------------- problem constants ----------------
#define Gn 4
#define Sn 2048
#define Dn 2048
#define En 64
#define NTOK (Gn*Sn)                  // 8192 tokens
#define NCOMB ((long long)NTOK*En*63) // 33,030,144 combine elements
#define MCTA 64
#define KC 64
#define KWG 16                        // chunks per warpgroup (2 wgs x 16 x 64 = 2048)
#define K1_THREADS 512
#define GEMM_BLOCKS (NTOK/MCTA)       // 128
#define K1_BLOCKS 148                 // 128 GEMM + 20 TMA-store CTAs
#define ZB 7                          // 16KB bulk-zero stores per chunk (GEMM CTAs)
#define ZBLKG ((long long)GEMM_BLOCKS*KWG*ZB)   // 14336 blocks covered by GEMM CTAs
#define ZBUF 65536                    // smem offset of 16KB zero buffer
#define SMEM_K1 81920

// ---------------- device scratch ----------------
__device__ int g_cnt[8*32*En];        // [gk][blk][expert] counts
__device__ int g_arrive;              // all-CTAs stores-visible arrivals
__device__ int g_depart;              // scatter departures (reset for replay)

__device__ __forceinline__ int ld_acq(const int* p) {
    int v;
    asm volatile("ld.acquire.gpu.s32 %0, [%1];" : "=r"(v) : "l"(p) : "memory");
    return v;
}

// swizzled byte offset inside a 64x64-bf16 tile (128B rows, XOR-16B swizzle)
__device__ __forceinline__ unsigned swz(int row, int chunk) {
    return (unsigned)(row*128 + ((chunk ^ (row & 7)) << 4));
}

// ---- TMA bulk zero store: smem -> global, 16KB ----
__device__ __forceinline__ void bulk_zero(float* gdst, unsigned s_src) {
    asm volatile("cp.async.bulk.global.shared::cta.bulk_group [%0], [%1], %2;"
                 :: "l"(gdst), "r"(s_src), "r"(16384u) : "memory");
}
#define BULK_COMMIT() asm volatile("cp.async.bulk.commit_group;" ::: "memory")
#define BULK_WAIT0()  asm volatile("cp.async.bulk.wait_group 0;" ::: "memory")
#define FENCE_ASYNC() asm volatile("fence.proxy.async.shared::cta;" ::: "memory")

#define LDSM4(R0_,R1_,R2_,R3_,ADDR) \
  asm volatile("ldmatrix.sync.aligned.m8n8.x4.shared.b16 {%0,%1,%2,%3}, [%4];" \
    : "=r"(R0_),"=r"(R1_),"=r"(R2_),"=r"(R3_) : "r"(ADDR))
#define LDSM4T(R0_,R1_,R2_,R3_,ADDR) \
  asm volatile("ldmatrix.sync.aligned.m8n8.x4.trans.shared.b16 {%0,%1,%2,%3}, [%4];" \
    : "=r"(R0_),"=r"(R1_),"=r"(R2_),"=r"(R3_) : "r"(ADDR))
#define HMMA(C_,A0,A1,A2,A3,B0,B1) \
  asm volatile("mma.sync.aligned.m16n8k16.row.col.f32.bf16.bf16.f32 " \
    "{%0,%1,%2,%3}, {%4,%5,%6,%7}, {%8,%9}, {%0,%1,%2,%3};" \
    : "+f"(C_[0]),"+f"(C_[1]),"+f"(C_[2]),"+f"(C_[3]) \
    : "r"(A0),"r"(A1),"r"(A2),"r"(A3),"r"(B0),"r"(B1))

// ===== K1: TMA zero-fill + GEMM + softmax/top2 + scan + barrier + scatter =====
__global__ void __launch_bounds__(K1_THREADS)
k1_fused(const float* __restrict__ x, const float* __restrict__ W,
         const float* __restrict__ b, float* __restrict__ out, long long out_n,
         const int* __restrict__ capp, int has_mask)
{
    const int tid = threadIdx.x;
    const long long nblk = out_n >> 12;       // 16KB blocks (4096 floats each)
    extern __shared__ __align__(16) unsigned char smx[];

    // ---- dedicated TMA-store CTAs: push tail blocks, arrive, exit ----
    if (blockIdx.x >= GEMM_BLOCKS) {
        for (int i = tid; i < 4096; i += K1_THREADS) ((float*)smx)[i] = 0.f;
        __syncthreads();
        if (tid == 0) {
            FENCE_ASYNC();
            unsigned zsrc = (unsigned)__cvta_generic_to_shared(smx);
            for (long long zi = ZBLKG + (blockIdx.x - GEMM_BLOCKS); zi < nblk;
                 zi += (K1_BLOCKS - GEMM_BLOCKS)) {
                bulk_zero(out + zi*4096, zsrc);
                BULK_COMMIT();
            }
            BULK_WAIT0();                      // globally visible
            __threadfence();
            atomicAdd(&g_arrive, 1);
        }
        return;
    }

    const int wg   = tid >> 8;          // warpgroup 0/1 (splits K)
    const int wtid = tid & 255;
    unsigned char* sm = smx + wg*32768;
    const unsigned sb = (unsigned)__cvta_generic_to_shared(sm);
    const unsigned XH = 0, XL = 8192, WHs = 16384, WLs = 24576;

    const int T0   = blockIdx.x * MCTA;
    const int lane = tid & 31;
    const int ww   = (tid >> 5) & 7;    // warp within warpgroup
    const int R0 = (ww & 3) * 16;       // 16 token rows per warp
    const int C0 = (ww >> 2) * 32;      // 32 experts per warp

    // init 16KB zero buffer + scalar tail zeros
    for (int i = tid; i < 4096; i += K1_THREADS) ((float*)(smx + ZBUF))[i] = 0.f;
    if (blockIdx.x == 0)
        for (long long i = nblk*4096 + tid; i < out_n; i += K1_THREADS) out[i] = 0.f;

    float acc[4][4];
#pragma unroll
    for (int i = 0; i < 4; ++i)
#pragma unroll
        for (int j = 0; j < 4; ++j) acc[i][j] = 0.f;

    const int dbase = wg * (KWG*KC);    // wg0: 0, wg1: 1024

    // prefetch chunk 0 of this warpgroup
    float2 xv[8], wv[8];
#pragma unroll
    for (int i = 0; i < 8; ++i) {
        int idx = wtid + 256*i;
        int row = idx >> 5, p = idx & 31;
        xv[i] = *(const float2*)(x + (size_t)(T0 + row)*Dn + dbase + 2*p);
        wv[i] = *(const float2*)(W + (size_t)(dbase + row)*En + 2*p);
    }

    __syncthreads();                          // zero buffer ready
    const unsigned zsrc = (unsigned)__cvta_generic_to_shared(smx + ZBUF);
    if (tid == 0) FENCE_ASYNC();

    const int lm = lane >> 3;
    const int lr = lane & 7;
    const int arow = R0 + ((lm & 1) << 3) + lr;
    const int half = lm >> 1;

    for (int c = 0; c < KWG; ++c) {
        __syncthreads();                      // tiles free
#pragma unroll
        for (int i = 0; i < 8; ++i) {
            int idx = wtid + 256*i;
            int row = idx >> 5, p = idx & 31;
            unsigned off = swz(row, p >> 2) + ((p & 3) << 2);
            __nv_bfloat162 h, l;
            h.x = __float2bfloat16(xv[i].x);
            h.y = __float2bfloat16(xv[i].y);
            l.x = __float2bfloat16(xv[i].x - __bfloat162float(h.x));
            l.y = __float2bfloat16(xv[i].y - __bfloat162float(h.y));
            *(__nv_bfloat162*)(sm + XH + off) = h;
            *(__nv_bfloat162*)(sm + XL + off) = l;
            h.x = __float2bfloat16(wv[i].x);
            h.y = __float2bfloat16(wv[i].y);
            l.x = __float2bfloat16(wv[i].x - __bfloat162float(h.x));
            l.y = __float2bfloat16(wv[i].y - __bfloat162float(h.y));
            *(__nv_bfloat162*)(sm + WHs + off) = h;
            *(__nv_bfloat162*)(sm + WLs + off) = l;
        }
        if (c + 1 < KWG) {
            const int dc0 = dbase + (c + 1)*KC;
#pragma unroll
            for (int i = 0; i < 8; ++i) {
                int idx = wtid + 256*i;
                int row = idx >> 5, p = idx & 31;
                xv[i] = *(const float2*)(x + (size_t)(T0 + row)*Dn + dc0 + 2*p);
                wv[i] = *(const float2*)(W + (size_t)(dc0 + row)*En + 2*p);
            }
        }
        // zero-fill: thread 0 hands 7 x 16KB blocks to the TMA engine
        if (tid == 0) {
#pragma unroll
            for (int j = 0; j < ZB; ++j) {
                long long zi = (long long)blockIdx.x + (long long)(c*ZB + j)*GEMM_BLOCKS;
                if (zi < nblk) bulk_zero(out + zi*4096, zsrc);
            }
            BULK_COMMIT();
        }
        __syncthreads();                      // tiles ready

#pragma unroll
        for (int ks = 0; ks < 4; ++ks) {
            unsigned ah0,ah1,ah2,ah3, al0,al1,al2,al3;
            const unsigned aoff = swz(arow, 2*ks + half);
            LDSM4(ah0,ah1,ah2,ah3, sb + XH + aoff);
            LDSM4(al0,al1,al2,al3, sb + XL + aoff);
            const int krow = 16*ks + ((lm & 1) << 3) + lr;
            unsigned bh[8], bl[8];
            const unsigned boff0 = swz(krow, (C0 >> 3) + half);
            const unsigned boff1 = swz(krow, (C0 >> 3) + 2 + half);
            LDSM4T(bh[0],bh[1],bh[2],bh[3], sb + WHs + boff0);
            LDSM4T(bh[4],bh[5],bh[6],bh[7], sb + WHs + boff1);
            LDSM4T(bl[0],bl[1],bl[2],bl[3], sb + WLs + boff0);
            LDSM4T(bl[4],bl[5],bl[6],bl[7], sb + WLs + boff1);
#pragma unroll
            for (int nt = 0; nt < 4; ++nt) {
                HMMA(acc[nt], ah0,ah1,ah2,ah3, bh[2*nt], bh[2*nt+1]);
                HMMA(acc[nt], ah0,ah1,ah2,ah3, bl[2*nt], bl[2*nt+1]);
                HMMA(acc[nt], al0,al1,al2,al3, bh[2*nt], bh[2*nt+1]);
            }
        }
    }

    if (tid == 0) BULK_WAIT0();               // our zero stores globally visible

    // ---- epilogue: wg0 writes partial logits, wg1 accumulates ----
    __syncthreads();                          // all tile reads done; reuse smx
    float* lg = (float*)smx;                  // [64][64] (16 KB)
    unsigned char* se    = smx + 16384;       // [2][64] expert idx per slot
    unsigned char* lpos  = smx + 16544;       // [2][64] local position
    int*           cntl  = (int*)(smx + 16768);   // [2][64] per-expert counts
    int*           baseS = (int*)(smx + 17408);   // [2][64] scatter base
    float*         sgate = (float*)(smx + 18048); // [2][64] gate values
    {
        const int g = lane >> 2, cc = (lane & 3)*2;
        if (wg == 0) {
#pragma unroll
            for (int nt = 0; nt < 4; ++nt) {
                int e = C0 + nt*8 + cc;
                lg[(R0 + g)*En + e]         = acc[nt][0];
                lg[(R0 + g)*En + e + 1]     = acc[nt][1];
                lg[(R0 + g + 8)*En + e]     = acc[nt][2];
                lg[(R0 + g + 8)*En + e + 1] = acc[nt][3];
            }
        }
        __syncthreads();
        if (wg == 1) {
#pragma unroll
            for (int nt = 0; nt < 4; ++nt) {
                int e = C0 + nt*8 + cc;
                lg[(R0 + g)*En + e]         += acc[nt][0];
                lg[(R0 + g)*En + e + 1]     += acc[nt][1];
                lg[(R0 + g + 8)*En + e]     += acc[nt][2];
                lg[(R0 + g + 8)*En + e + 1] += acc[nt][3];
            }
        }
    }
    __syncthreads();

    // ---- softmax + top2: 16 warps x 4 rows ----
    {
        float2 bb = ((const float2*)b)[lane];
        const int e0 = 2*lane, e1 = 2*lane + 1;
        const int wglob = tid >> 5;           // 0..15
        for (int r = wglob*4; r < wglob*4 + 4; ++r) {
            float2 v = *(float2*)&lg[r*En + 2*lane];
            float l0 = v.x + bb.x, l1 = v.y + bb.y;

            float m = fmaxf(l0, l1);
#pragma unroll
            for (int o = 16; o > 0; o >>= 1) m = fmaxf(m, __shfl_xor_sync(0xffffffffu, m, o));
            float p0 = expf(l0 - m), p1 = expf(l1 - m);
            float s = p0 + p1;
#pragma unroll
            for (int o = 16; o > 0; o >>= 1) s += __shfl_xor_sync(0xffffffffu, s, o);
            p0 = p0 / s;
            p1 = p1 / s;

            float wp; int we;
            if (p1 > p0) { wp = p1; we = e1; } else { wp = p0; we = e0; }
#pragma unroll
            for (int o = 16; o > 0; o >>= 1) {
                float op = __shfl_xor_sync(0xffffffffu, wp, o);
                int   oe = __shfl_xor_sync(0xffffffffu, we, o);
                if (op > wp || (op == wp && oe < we)) { wp = op; we = oe; }
            }
            float a0 = (e0 == we) ? -1.f : p0;
            float a1 = (e1 == we) ? -1.f : p1;
            float wp2; int we2;
            if (a1 > a0) { wp2 = a1; we2 = e1; } else { wp2 = a0; we2 = e0; }
#pragma unroll
            for (int o = 16; o > 0; o >>= 1) {
                float op = __shfl_xor_sync(0xffffffffu, wp2, o);
                int   oe = __shfl_xor_sync(0xffffffffu, we2, o);
                if (op > wp2 || (op == wp2 && oe < we2)) { wp2 = op; we2 = oe; }
            }
            if (lane == 0) {
                se[r]         = (unsigned char)we;
                se[64 + r]    = (unsigned char)we2;
                sgate[r]      = wp;
                sgate[64 + r] = wp2;
            }
        }
    }
    __syncthreads();

    // ---- block-local rank scan for both slots (warps 0 and 1) ----
    if (tid < 128) cntl[tid] = 0;
    __syncthreads();
    if ((tid >> 5) < 2) {
        const int slot = tid >> 5;
#pragma unroll
        for (int it = 0; it < 2; ++it) {
            int t = it*32 + lane;
            int e = se[slot*64 + t];
            unsigned mask = __match_any_sync(0xffffffffu, e);
            int rank = __popc(mask & ((1u << lane) - 1u));
            int base = cntl[slot*64 + e];
            lpos[slot*64 + t] = (unsigned char)(base + rank);
            __syncwarp();
            if (rank == 0) cntl[slot*64 + e] = base + __popc(mask);
            __syncwarp();
        }
    }
    __syncthreads();

    const int gidx = T0 >> 11;              // group = T0 / Sn
    const int blk  = (T0 & (Sn - 1)) >> 6;  // 64-token block within group
    if (tid < 128) {
        int k = tid >> 6, e = tid & 63;
        g_cnt[((gidx*2 + k)*32 + blk)*En + e] = cntl[k*64 + e];
    }

    // ---- publish counts (tiny fence) + device-wide arrive/wait ----
    __threadfence();
    __syncthreads();
    if (tid == 0) {
        atomicAdd(&g_arrive, 1);
        while (ld_acq(&g_arrive) < K1_BLOCKS) { }
    }
    __syncthreads();

    // ---- per-expert base = sum of counts of earlier blocks in this (g,k) ----
    if (tid < 128) {
        int k = tid >> 6, e = tid & 63;
        const int gkk = gidx*2 + k;
        int a = 0;
        for (int bq = 0; bq < blk; ++bq)
            a += g_cnt[(gkk*32 + bq)*En + e];
        baseS[k*64 + e] = a;
    }
    __syncthreads();

    // ---- scatter this CTA's 64 tokens x 2 slots ----
    int cap = 64;
    if (capp) { cap = capp[0]; if (cap > 64) cap = 64; }
    if (tid < 128) {
        int k = tid >> 6, r = tid & 63;
        int   e    = se[k*64 + r];
        float gate = sgate[k*64 + r];
        int   pos0 = baseS[k*64 + e] + (int)lpos[k*64 + r];
        if (pos0 + 1 < cap) {
            long long t   = (long long)(T0 + r);
            long long off = (t*En + e)*63 + pos0;
            if (off < out_n) out[off] = gate;
            if (has_mask) {
                long long moff = NCOMB + off;
                if (moff < out_n) out[moff] = (gate != 0.f) ? 1.f : 0.f;
            }
        }
    }

    // ---- departure: last GEMM CTA resets barriers for the next replay ----
    __syncthreads();
    if (tid == 0) {
        int d = atomicAdd(&g_depart, 1);
        if (d == GEMM_BLOCKS - 1) {
            g_arrive = 0;
            __threadfence();
            g_depart = 0;
        }
    }
}

// ================= launch =================
extern "C" void kernel_launch(void* const* d_in, const int* in_sizes, int n_in,
                              void* d_out, int out_size)
{
    const float* x = (const float*)d_in[0];
    const float* W = (const float*)d_in[1];
    const float* b = (const float*)d_in[2];
    const int* capp = (n_in >= 4) ? (const int*)d_in[3] : nullptr;
    float* out = (float*)d_out;
    long long out_n = (long long)out_size;
    int has_mask = (out_n >= 2LL*NCOMB) ? 1 : 0;

    cudaFuncSetAttribute(k1_fused, cudaFuncAttributeMaxDynamicSharedMemorySize, SMEM_K1);
    k1_fused<<<K1_BLOCKS, K1_THREADS, SMEM_K1>>>(x, W, b, out, out_n, capp, has_mask);
}